// round 6
// baseline (speedup 1.0000x reference)
#include <cuda_runtime.h>
#include <cuda_fp16.h>
#include <math.h>
#include <stdint.h>

// ---------------------------------------------------------------------------
// GTN: H = diag(s) * HA * (HB*HB2), union-sparse pattern, SMEM-staged SpMM.
// k-sorted CSR lists + per-chunk offsets -> CTA stages M[k-chunk, col-slice]
// in SMEM (double-buffered cp.async) and reuses it across 128 H rows.
// Output: y[512*8] | all_Ws[3*2*5] | H[2*2048*2048]
// ---------------------------------------------------------------------------

#define NN    2048
#define NE    5
#define NC    2
#define CAP   256
#define NT    512
#define XD    512
#define WOUT  128
#define NCLS  8

#define Y_OFF  0
#define WS_OFF (NT * NCLS)
#define H_OFF  (WS_OFF + 3 * NC * NE)   // 4126 floats (8B aligned)

// spmm tiling
#define RB  128                 // H rows per CTA
#define CS  256                 // H cols per CTA
#define KC  128                 // k per chunk
#define NCH (NN / KC)           // 16 chunks
#define SPMM_SMEM (2 * KC * CS * 2)   // 131072 bytes

// ------------------------- static device scratch ---------------------------
__device__ int    g_cnt[NN];
__device__ int    g_cols[NN * CAP];          // k-sorted column indices
__device__ int2   g_pa [NC][NN * CAP];       // packed {col, HA weight bits}
__device__ float  g_hav [NC][NN * CAP];
__device__ float  g_hbv [NC][NN * CAP];
__device__ float  g_hb2v[NC][NN * CAP];
__device__ int    g_coff[NN][NCH + 1];       // per-row chunk start indices (absolute)
__device__ float  g_s[3][NC][NE];
__device__ float  g_rB  [NC][NN];
__device__ float  g_rB2 [NC][NN];
__device__ float  g_rM  [NC][NN];
__device__ float  g_deg0[NC][NN];
__device__ float  g_scale[NC][NN];
__device__ __align__(16) __half g_Mh[NC][NN][NN];   // M = HB@HB2, fp16
__device__ float  g_gwT[XD][WOUT];

// ------------------------------ helpers ------------------------------------
__device__ __forceinline__ uint32_t smem_u32(const void* p) {
    uint32_t a;
    asm("{ .reg .u64 t; cvta.to.shared.u64 t, %1; cvt.u32.u64 %0, t; }" : "=r"(a) : "l"(p));
    return a;
}
__device__ __forceinline__ float warpSum(float v) {
    #pragma unroll
    for (int o = 16; o > 0; o >>= 1) v += __shfl_down_sync(0xffffffffu, v, o);
    return v;
}
__device__ __forceinline__ void cp_async16(uint32_t dst, const void* src) {
    asm volatile("cp.async.cg.shared.global [%0], [%1], 16;" :: "r"(dst), "l"(src) : "memory");
}

// --------------------------- kernel 1: init --------------------------------
__global__ void k_init(const float* __restrict__ w1, const float* __restrict__ w2,
                       const float* __restrict__ w3, float* __restrict__ out_ws) {
    int tid = threadIdx.x;
    if (tid < 3 * NC) {
        int m = tid / NC, c = tid % NC;
        const float* w = (m == 0 ? w1 : (m == 1 ? w2 : w3)) + c * NE;
        float mx = w[0];
        #pragma unroll
        for (int e = 1; e < NE; e++) mx = fmaxf(mx, w[e]);
        float ex[NE], s = 0.f;
        #pragma unroll
        for (int e = 0; e < NE; e++) { ex[e] = expf(w[e] - mx); s += ex[e]; }
        float inv = 1.f / s;
        #pragma unroll
        for (int e = 0; e < NE; e++) {
            float v = ex[e] * inv;
            g_s[m][c][e] = v;
            out_ws[m * NC * NE + c * NE + e] = v;
        }
    }
}

// ---- kernel 2: build k-SORTED sparse pattern + values (block scan) --------
__global__ void k_fill(const float* __restrict__ A) {
    int i = blockIdx.x;
    int tid = threadIdx.x, lane = tid & 31, w = tid >> 5;
    __shared__ int warpoff[8];
    __shared__ int base;
    if (tid == 0) base = 0;
    float s1[NC][NE], s2[NC][NE], s3[NC][NE];
    #pragma unroll
    for (int c = 0; c < NC; c++)
        #pragma unroll
        for (int e = 0; e < NE; e++) {
            s1[c][e] = g_s[0][c][e]; s2[c][e] = g_s[1][c][e]; s3[c][e] = g_s[2][c][e];
        }
    __syncthreads();
    for (int s = 0; s < 8; s++) {
        int j = s * 256 + tid;
        float a[NE];
        bool nz = false;
        #pragma unroll
        for (int e = 0; e < NE; e++) {
            a[e] = A[(size_t)e * NN * NN + (size_t)i * NN + j];
            nz |= (a[e] != 0.f);
        }
        unsigned mask = __ballot_sync(0xffffffffu, nz);
        if (lane == 0) warpoff[w] = __popc(mask);
        __syncthreads();
        int woff = 0;
        #pragma unroll
        for (int k = 0; k < 8; k++) if (k < w) woff += warpoff[k];
        int slot = base + woff + __popc(mask & ((1u << lane) - 1u));
        if (nz && slot < CAP) {
            int p = i * CAP + slot;
            g_cols[p] = j;
            #pragma unroll
            for (int c = 0; c < NC; c++) {
                float va = 0.f, vb = 0.f, vb2 = 0.f;
                #pragma unroll
                for (int e = 0; e < NE; e++) {
                    va  += s1[c][e] * a[e];
                    vb  += s2[c][e] * a[e];
                    vb2 += s3[c][e] * a[e];
                }
                g_hav[c][p] = va; g_hbv[c][p] = vb; g_hb2v[c][p] = vb2;
                g_pa[c][p] = make_int2(j, __float_as_int(va));
            }
        }
        __syncthreads();
        if (tid == 0) {
            int tot = 0;
            #pragma unroll
            for (int k = 0; k < 8; k++) tot += warpoff[k];
            base += tot;
        }
        __syncthreads();
    }
    if (tid == 0) g_cnt[i] = min(base, CAP);
}

// ---- kernel 2b: per-row per-chunk offsets ---------------------------------
__global__ void k_coff() {
    int i = blockIdx.x;
    __shared__ int hist[NCH];
    if (threadIdx.x < NCH) hist[threadIdx.x] = 0;
    __syncthreads();
    int cnt = g_cnt[i];
    for (int t = threadIdx.x; t < cnt; t += blockDim.x)
        atomicAdd(&hist[g_cols[i * CAP + t] / KC], 1);
    __syncthreads();
    if (threadIdx.x == 0) {
        int run = i * CAP;
        #pragma unroll
        for (int k = 0; k < NCH; k++) { g_coff[i][k] = run; run += hist[k]; }
        g_coff[i][NCH] = run;
    }
}

// --------------- kernel 3: row sums of HB, HB2 -----------------------------
__global__ void k_rowstats() {
    int r = blockIdx.x;
    int cnt = min(g_cnt[r], CAP);
    float a0 = 0, a1 = 0, b0 = 0, b1 = 0;
    for (int t = threadIdx.x; t < cnt; t += blockDim.x) {
        int p = r * CAP + t;
        a0 += g_hbv[0][p];  a1 += g_hbv[1][p];
        b0 += g_hb2v[0][p]; b1 += g_hb2v[1][p];
    }
    a0 = warpSum(a0); a1 = warpSum(a1); b0 = warpSum(b0); b1 = warpSum(b1);
    __shared__ float sh[4][4];
    int w = threadIdx.x >> 5, lane = threadIdx.x & 31;
    if (lane == 0) { sh[w][0] = a0; sh[w][1] = a1; sh[w][2] = b0; sh[w][3] = b1; }
    __syncthreads();
    if (threadIdx.x == 0) {
        float v0 = 0, v1 = 0, v2 = 0, v3 = 0;
        for (int k = 0; k < 4; k++) { v0 += sh[k][0]; v1 += sh[k][1]; v2 += sh[k][2]; v3 += sh[k][3]; }
        g_rB[0][r] = v0; g_rB[1][r] = v1; g_rB2[0][r] = v2; g_rB2[1][r] = v3;
    }
}

// ---- kernel 4: deg0 + rowsum(M) -------------------------------------------
__global__ void k_deg() {
    int r = blockIdx.x;
    int cnt = min(g_cnt[r], CAP);
    float d0 = 0, d1 = 0, m0 = 0, m1 = 0;
    for (int t = threadIdx.x; t < cnt; t += blockDim.x) {
        int p = r * CAP + t;
        int col = g_cols[p];
        d0 += g_hav[0][p] * g_rB[0][col];
        d1 += g_hav[1][p] * g_rB[1][col];
        m0 += g_hbv[0][p] * g_rB2[0][col];
        m1 += g_hbv[1][p] * g_rB2[1][col];
    }
    d0 = warpSum(d0); d1 = warpSum(d1); m0 = warpSum(m0); m1 = warpSum(m1);
    __shared__ float sh[4][4];
    int w = threadIdx.x >> 5, lane = threadIdx.x & 31;
    if (lane == 0) { sh[w][0] = d0; sh[w][1] = d1; sh[w][2] = m0; sh[w][3] = m1; }
    __syncthreads();
    if (threadIdx.x == 0) {
        float v0 = 0, v1 = 0, v2 = 0, v3 = 0;
        for (int k = 0; k < 4; k++) { v0 += sh[k][0]; v1 += sh[k][1]; v2 += sh[k][2]; v3 += sh[k][3]; }
        g_deg0[0][r] = v0; g_deg0[1][r] = v1; g_rM[0][r] = v2; g_rM[1][r] = v3;
    }
}

// ---- kernel 5: final per-row scale ----------------------------------------
__global__ void k_scalek() {
    int r = blockIdx.x;
    int cnt = min(g_cnt[r], CAP);
    float t0 = 0, t1 = 0;
    for (int t = threadIdx.x; t < cnt; t += blockDim.x) {
        int p = r * CAP + t;
        int col = g_cols[p];
        t0 += g_hav[0][p] * g_rM[0][col];
        t1 += g_hav[1][p] * g_rM[1][col];
    }
    t0 = warpSum(t0); t1 = warpSum(t1);
    __shared__ float sh[4][2];
    int w = threadIdx.x >> 5, lane = threadIdx.x & 31;
    if (lane == 0) { sh[w][0] = t0; sh[w][1] = t1; }
    __syncthreads();
    if (threadIdx.x == 0) {
        float tt[2] = {0.f, 0.f};
        for (int k = 0; k < 4; k++) { tt[0] += sh[k][0]; tt[1] += sh[k][1]; }
        #pragma unroll
        for (int c = 0; c < NC; c++) {
            float dg0 = g_deg0[c][r];
            float d0 = (dg0 > 0.f) ? (1.f / sqrtf(dg0)) : 0.f;
            float dg1 = d0 * tt[c];
            float d1 = (dg1 > 0.f) ? (1.f / sqrtf(dg1)) : 0.f;
            g_scale[c][r] = d0 * d1;
        }
    }
}

// ---------- kernel 6: M = HB @ HB2 (sparse x sparse -> dense fp16) ---------
__global__ void k_M() {
    int k = blockIdx.x, c = blockIdx.y;
    __shared__ float acc[NN];
    for (int j = threadIdx.x; j < NN; j += blockDim.x) acc[j] = 0.f;
    __syncthreads();
    int cnt = min(g_cnt[k], CAP);
    int warp = threadIdx.x >> 5, lane = threadIdx.x & 31;
    for (int pi = warp; pi < cnt; pi += 8) {
        int p = k * CAP + pi;
        int l = g_cols[p];
        float hb = g_hbv[c][p];
        int cl = min(g_cnt[l], CAP);
        for (int qi = lane; qi < cl; qi += 32) {
            int q = l * CAP + qi;
            atomicAdd(&acc[g_cols[q]], hb * g_hb2v[c][q]);
        }
    }
    __syncthreads();
    __half2* mrow = reinterpret_cast<__half2*>(&g_Mh[c][k][0]);
    for (int j2 = threadIdx.x; j2 < NN / 2; j2 += blockDim.x)
        mrow[j2] = __floats2half2_rn(acc[2 * j2], acc[2 * j2 + 1]);
}

// ---------- kernel 7: SMEM-staged SpMM: H = diag(scale)*(HA @ M) -----------
// CTA: 128 rows x 256 cols; k chunks of 128 staged fp16 in SMEM, double buf.
// 16 warps; warp handles 8 rows; lane owns 8 cols; acc[8][8] fp32.
__global__ void __launch_bounds__(512, 1) k_spmm2(float* __restrict__ H) {
    extern __shared__ __align__(16) char dsm[];
    const uint32_t sb = smem_u32(dsm);
    const int c = blockIdx.z;
    const int rowbase = blockIdx.y * RB;
    const int colbase = blockIdx.x * CS;
    const int tid = threadIdx.x, lane = tid & 31, w = tid >> 5;

    float acc[8][8];
    #pragma unroll
    for (int r = 0; r < 8; r++)
        #pragma unroll
        for (int q = 0; q < 8; q++) acc[r][q] = 0.f;

    // chunk loader: 512 threads, KC=128 k-rows of 512B each (4 thr/row, 128B ea)
    const int lkr = tid >> 2, lof = (tid & 3) * 64;   // halves offset within row
    auto load_chunk = [&](int buf, int n) {
        const int k0 = n * KC;
        uint32_t dst = sb + buf * (KC * CS * 2) + (uint32_t)lkr * (CS * 2) + lof * 2;
        const __half* src = &g_Mh[c][k0 + lkr][colbase + lof];
        #pragma unroll
        for (int q = 0; q < 8; q++)
            cp_async16(dst + q * 16, src + q * 8);
        asm volatile("cp.async.commit_group;" ::: "memory");
    };

    load_chunk(0, 0);
    for (int n = 0; n < NCH; n++) {
        if (n + 1 < NCH) {
            load_chunk((n + 1) & 1, n + 1);
            asm volatile("cp.async.wait_group 1;" ::: "memory");
        } else {
            asm volatile("cp.async.wait_group 0;" ::: "memory");
        }
        __syncthreads();
        const __half* Mb = reinterpret_cast<const __half*>(dsm + (n & 1) * (KC * CS * 2));
        const int k0 = n * KC;
        #pragma unroll
        for (int rw = 0; rw < 8; rw++) {
            const int row = rowbase + w * 8 + rw;
            const int pb = g_coff[row][n];
            const int pe = g_coff[row][n + 1];
            for (int p = pb; p < pe; p++) {
                int2 e = g_pa[c][p];                      // broadcast (uniform)
                float wv = __int_as_float(e.y);
                const uint4 mv = *reinterpret_cast<const uint4*>(
                    Mb + (e.x - k0) * CS + lane * 8);
                __half2 h0 = *reinterpret_cast<const __half2*>(&mv.x);
                __half2 h1 = *reinterpret_cast<const __half2*>(&mv.y);
                __half2 h2 = *reinterpret_cast<const __half2*>(&mv.z);
                __half2 h3 = *reinterpret_cast<const __half2*>(&mv.w);
                float2 f0 = __half22float2(h0), f1 = __half22float2(h1);
                float2 f2 = __half22float2(h2), f3 = __half22float2(h3);
                acc[rw][0] += wv * f0.x; acc[rw][1] += wv * f0.y;
                acc[rw][2] += wv * f1.x; acc[rw][3] += wv * f1.y;
                acc[rw][4] += wv * f2.x; acc[rw][5] += wv * f2.y;
                acc[rw][6] += wv * f3.x; acc[rw][7] += wv * f3.y;
            }
        }
        __syncthreads();
    }

    // epilogue: scale + store (float2, 8B-aligned at H_OFF)
    #pragma unroll
    for (int rw = 0; rw < 8; rw++) {
        const int row = rowbase + w * 8 + rw;
        const float sc = g_scale[c][row];
        float* out = &H[(size_t)c * NN * NN + (size_t)row * NN + colbase + lane * 8];
        #pragma unroll
        for (int q = 0; q < 4; q++) {
            float2 v = make_float2(sc * acc[rw][2 * q], sc * acc[rw][2 * q + 1]);
            reinterpret_cast<float2*>(out)[q] = v;
        }
    }
}

// -------------------- kernel 8: transpose gcn_w ----------------------------
__global__ void k_transpose(const float* __restrict__ gw) {
    int idx = blockIdx.x * blockDim.x + threadIdx.x;
    if (idx < WOUT * XD) {
        int jj = idx / XD, kk = idx % XD;
        g_gwT[kk][jj] = gw[idx];
    }
}

// -------------------- kernel 9: classification head ------------------------
__global__ void k_head(const float* __restrict__ Xm, const float* __restrict__ gcn_b,
                       const float* __restrict__ lin_w, const float* __restrict__ lin_b,
                       const int* __restrict__ tx, float* __restrict__ y) {
    int t = blockIdx.x;
    int row = tx[t];
    __shared__ float xr[XD];
    __shared__ float h[WOUT];
    for (int k = threadIdx.x; k < XD; k += blockDim.x)
        xr[k] = Xm[(size_t)row * XD + k];
    __syncthreads();
    int j = threadIdx.x;
    float acc = gcn_b[j];
    #pragma unroll 8
    for (int k = 0; k < XD; k++) acc += g_gwT[k][j] * xr[k];
    h[j] = fmaxf(acc, 0.f);
    __syncthreads();
    if (j < NCLS) {
        float acc2 = lin_b[j];
        #pragma unroll 4
        for (int m = 0; m < WOUT; m++)
            acc2 += (lin_w[j * (NC * WOUT) + m] + lin_w[j * (NC * WOUT) + WOUT + m]) * h[m];
        y[t * NCLS + j] = acc2;
    }
}

// ------------------------------ launch -------------------------------------
extern "C" void kernel_launch(void* const* d_in, const int* in_sizes, int n_in,
                              void* d_out, int out_size) {
    const float* A     = (const float*)d_in[0];
    const float* X     = (const float*)d_in[1];
    const float* w01   = (const float*)d_in[2];
    const float* w02   = (const float*)d_in[3];
    const float* w11   = (const float*)d_in[4];
    const float* gcn_w = (const float*)d_in[5];
    const float* gcn_b = (const float*)d_in[6];
    const float* lin_w = (const float*)d_in[7];
    const float* lin_b = (const float*)d_in[8];
    const int*   tx    = (const int*)d_in[9];
    float* out = (float*)d_out;

    cudaFuncSetAttribute(k_spmm2, cudaFuncAttributeMaxDynamicSharedMemorySize, SPMM_SMEM);

    k_init<<<1, 32>>>(w01, w02, w11, out + WS_OFF);
    k_fill<<<NN, 256>>>(A);
    k_coff<<<NN, 128>>>();
    k_rowstats<<<NN, 128>>>();
    k_deg<<<NN, 128>>>();
    k_scalek<<<NN, 128>>>();
    k_M<<<dim3(NN, NC), 256>>>();
    k_spmm2<<<dim3(NN / CS, NN / RB, NC), 512, SPMM_SMEM>>>(out + H_OFF);
    k_transpose<<<(WOUT * XD + 255) / 256, 256>>>(gcn_w);
    k_head<<<NT, 128>>>(X, gcn_b, lin_w, lin_b, tx, out + Y_OFF);
}